// round 14
// baseline (speedup 1.0000x reference)
#include <cuda_runtime.h>
#include <cuda_fp16.h>
#include <stdint.h>

#define NHEAD 8
#define DMODEL 512
#define MAXELEMS (4*2048*512)

// Scratch (allocation-free rule: __device__ globals) — fp16 activations
__device__ __half g_qph[MAXELEMS];   // pre-scaled by 0.125*log2(e)
__device__ __half g_kph[MAXELEMS];
__device__ __half g_vph[MAXELEMS];
__device__ __half g_ctxh[MAXELEMS];
__device__ __half g_woh[DMODEL * DMODEL];

// ---------------------------------------------------------------------------
// fp16 mma + ldmatrix helpers (legacy path: valid on plain sm_103 target)
// ---------------------------------------------------------------------------
__device__ __forceinline__ void mma16(float c[4], const unsigned a[4],
                                      unsigned b0, unsigned b1) {
    asm volatile("mma.sync.aligned.m16n8k16.row.col.f32.f16.f16.f32 "
                 "{%0,%1,%2,%3}, {%4,%5,%6,%7}, {%8,%9}, {%0,%1,%2,%3};"
                 : "+f"(c[0]), "+f"(c[1]), "+f"(c[2]), "+f"(c[3])
                 : "r"(a[0]), "r"(a[1]), "r"(a[2]), "r"(a[3]), "r"(b0), "r"(b1));
}
__device__ __forceinline__ void ldmat4(unsigned& r0, unsigned& r1,
                                       unsigned& r2, unsigned& r3, unsigned addr) {
    asm volatile("ldmatrix.sync.aligned.m8n8.x4.shared.b16 {%0,%1,%2,%3}, [%4];"
                 : "=r"(r0), "=r"(r1), "=r"(r2), "=r"(r3) : "r"(addr));
}
__device__ __forceinline__ void ldmat4t(unsigned& r0, unsigned& r1,
                                        unsigned& r2, unsigned& r3, unsigned addr) {
    asm volatile("ldmatrix.sync.aligned.m8n8.x4.trans.shared.b16 {%0,%1,%2,%3}, [%4];"
                 : "=r"(r0), "=r"(r1), "=r"(r2), "=r"(r3) : "r"(addr));
}
__device__ __forceinline__ unsigned pkh2(float a, float b) {
    __half2 h = __floats2half2_rn(a, b);
    return *reinterpret_cast<unsigned*>(&h);
}
__device__ __forceinline__ unsigned ex2h2(unsigned x) {
    unsigned r;
    asm("ex2.approx.f16x2 %0, %1;" : "=r"(r) : "r"(x));
    return r;
}
__device__ __forceinline__ unsigned hmul2u(unsigned a, unsigned b) {
    __half2 r = __hmul2(*reinterpret_cast<__half2*>(&a), *reinterpret_cast<__half2*>(&b));
    return *reinterpret_cast<unsigned*>(&r);
}
__device__ __forceinline__ float2 h2f2(unsigned a) {
    return __half22float2(*reinterpret_cast<__half2*>(&a));
}

// cp.async helpers
__device__ __forceinline__ void cp16(unsigned dst, const void* src) {
    asm volatile("cp.async.cg.shared.global [%0], [%1], 16;" :: "r"(dst), "l"(src));
}
#define CP_COMMIT() asm volatile("cp.async.commit_group;" ::: "memory")
#define CP_WAIT(n)  asm volatile("cp.async.wait_group %0;" :: "n"(n) : "memory")

// pane row stride: 72 halfs (36 half2; 36 mod 32 = 4 -> conflict-free frags;
// 144 B rows = 9 x 16B -> ldmatrix-aligned, conflict-free phases)
#define PSTR 72
#define PSTR2 36

// ---------------------------------------------------------------------------
// Kernel 0: one-time Wo fp32 -> fp16 (512x512 = 512 KB out)
// ---------------------------------------------------------------------------
__global__ __launch_bounds__(256) void cvt_wo(const float* __restrict__ Wo) {
    int i = (blockIdx.x * 256 + threadIdx.x) * 4;
    float4 a = *(const float4*)(Wo + i);
    *(uint2*)&g_woh[i] = make_uint2(pkh2(a.x, a.y), pkh2(a.z, a.w));
}

// ---------------------------------------------------------------------------
// Kernel 1: projections (x viewed as [BS*8, 64] rows; W shared across heads).
// 2 row-blocks per CTA with register prefetch: block t+1's LDGs issue right
// after block t's barrier, hiding gmem latency under ldmatrix+mma+store.
// Double A panes; W staged once. q output pre-scaled by 0.125*log2(e).
// ---------------------------------------------------------------------------
#define PBLK 2

__global__ __launch_bounds__(256) void proj_tc(
    const float* __restrict__ q, const float* __restrict__ k, const float* __restrict__ v,
    const float* __restrict__ Wq, const float* __restrict__ Wk, const float* __restrict__ Wv,
    const float* __restrict__ bq, const float* __restrict__ bk, const float* __restrict__ bv)
{
    extern __shared__ char smc[];
    __half* A0 = (__half*)smc;                      // [128][72]
    __half* A1 = (__half*)smc + 128 * PSTR;         // [128][72]
    __half* Ws = (__half*)smc + 2 * 128 * PSTR;     // [64][72]

    const int tid = threadIdx.x, w = tid >> 5, lid = tid & 31;
    const int g = lid >> 2, t4 = lid & 3;
    const int lm = lid >> 3, lr = lid & 7;
    const int which = blockIdx.y;
    const float* x  = which == 0 ? q  : which == 1 ? k  : v;
    const float* W  = which == 0 ? Wq : which == 1 ? Wk : Wv;
    const float* bb = which == 0 ? bq : which == 1 ? bk : bv;
    __half* dst = which == 0 ? g_qph : which == 1 ? g_kph : g_vph;
    const float scale = which == 0 ? 0.125f * 1.4426950408889634f : 1.0f;
    const long r0 = (long)blockIdx.x * (128 * PBLK);

    const int fr = tid >> 4, fc = tid & 15;   // staging coords (row, col4)

    // prefetch block 0 into registers
    float4 xr[8];
#pragma unroll
    for (int i = 0; i < 8; ++i)
        xr[i] = *(const float4*)(x + (r0 + fr + i * 16) * 64 + fc * 4);

    // stage W once
#pragma unroll
    for (int i = 0; i < 4; ++i) {
        int f = tid + i * 256, r = f >> 4, c = f & 15;
        float4 a = *(const float4*)(W + r * 64 + c * 4);
        *(uint2*)&Ws[r * PSTR + c * 4] = make_uint2(pkh2(a.x, a.y), pkh2(a.z, a.w));
    }

    const unsigned wbase = (unsigned)__cvta_generic_to_shared(Ws);
    __half* Apane[2] = {A0, A1};

#pragma unroll
    for (int t = 0; t < PBLK; ++t) {
        __half* As = Apane[t];
        // stage prefetched block t
#pragma unroll
        for (int i = 0; i < 8; ++i)
            *(uint2*)&As[(fr + i * 16) * PSTR + fc * 4] =
                make_uint2(pkh2(xr[i].x, xr[i].y), pkh2(xr[i].z, xr[i].w));
        __syncthreads();

        // prefetch block t+1 (hidden under this block's compute)
        if (t + 1 < PBLK) {
#pragma unroll
            for (int i = 0; i < 8; ++i)
                xr[i] = *(const float4*)(x + (r0 + (t + 1) * 128 + fr + i * 16) * 64 + fc * 4);
        }

        const unsigned abase = (unsigned)__cvta_generic_to_shared(As);
        float acc[8][4] = {};
#pragma unroll
        for (int kb = 0; kb < 4; ++kb) {
            unsigned af[4];
            unsigned aaddr = abase +
                ((16 * w + (lm & 1) * 8 + lr) * PSTR + kb * 16 + (lm >> 1) * 8) * 2u;
            ldmat4(af[0], af[1], af[2], af[3], aaddr);
#pragma unroll
            for (int np = 0; np < 4; ++np) {
                unsigned v0, v1, v2, v3;
                unsigned addr = wbase +
                    ((kb * 16 + (lm & 1) * 8 + lr) * PSTR + np * 16 + (lm >> 1) * 8) * 2u;
                ldmat4t(v0, v1, v2, v3, addr);
                mma16(acc[2 * np],     af, v0, v1);
                mma16(acc[2 * np + 1], af, v2, v3);
            }
        }

        const long row0 = (r0 + t * 128 + 16 * w + g) * 64;
        const long row1 = row0 + 8 * 64;
#pragma unroll
        for (int nb = 0; nb < 8; ++nb) {
            int c = nb * 8 + 2 * t4;
            float b0v = bb[c], b1v = bb[c + 1];
            *(unsigned*)(dst + row0 + c) = pkh2((acc[nb][0] + b0v) * scale, (acc[nb][1] + b1v) * scale);
            *(unsigned*)(dst + row1 + c) = pkh2((acc[nb][2] + b0v) * scale, (acc[nb][3] + b1v) * scale);
        }
        if (t + 1 < PBLK) __syncthreads();   // W/A pane ordering for next stage
    }
}

// ---------------------------------------------------------------------------
// Kernel 2: fp16 flash attention, triple-buffered K/V, ONE barrier per tile.
// l-sums on the FMA pipe (tensor pipe is the binding resource).
// ---------------------------------------------------------------------------
#define SMH_Q 0
#define SMH_SLOT (2 * 64 * PSTR)               // 9216 halfs per slot (K+V)
#define SMH_KV (128 * PSTR)                    // slots start after Q
#define SMH_TOTAL ((SMH_KV + 3 * SMH_SLOT) * 2)  // 73728 B

__device__ __forceinline__ void issue_tile_h(unsigned dstb, const __half* gsrc, int tid) {
#pragma unroll
    for (int i = 0; i < 2; ++i) {
        int f = tid + i * 256, r = f >> 3, c = f & 7;
        cp16(dstb + (unsigned)(r * PSTR + c * 8) * 2u, gsrc + (long)r * DMODEL + c * 8);
    }
}

__global__ __launch_bounds__(256, 2) void attn_mma(const int* __restrict__ valid_lens, int S)
{
    extern __shared__ char smc[];
    const unsigned smb = (unsigned)__cvta_generic_to_shared(smc);

    const int tid = threadIdx.x, w = tid >> 5, lid = tid & 31;
    const int g = lid >> 2, t4 = lid & 3;
    const int lm = lid >> 3, lr = lid & 7;

    const int h = blockIdx.y, b = blockIdx.z;
    const int s0 = blockIdx.x * 128;
    const int valid = valid_lens[b];
    const long gbase = (long)b * S * DMODEL + h * 64;
    const __half* kg = g_kph + gbase;
    const __half* vg = g_vph + gbase;

    const int nt = (valid + 63) >> 6;

    // G0: Q tile [128 x 64]
#pragma unroll
    for (int i = 0; i < 4; ++i) {
        int f = tid + i * 256, r = f >> 3, c = f & 7;
        cp16(smb + (unsigned)(SMH_Q + r * PSTR + c * 8) * 2u,
             g_qph + gbase + (long)(s0 + r) * DMODEL + c * 8);
    }
    CP_COMMIT();
    // G1: tile0 -> slot0; G2: tile1 -> slot1 (maybe empty)
    issue_tile_h(smb + SMH_KV * 2u, kg, tid);
    issue_tile_h(smb + (SMH_KV + 64 * PSTR) * 2u, vg, tid);
    CP_COMMIT();
    if (nt > 1) {
        issue_tile_h(smb + (SMH_KV + SMH_SLOT) * 2u, kg + 64 * DMODEL, tid);
        issue_tile_h(smb + (SMH_KV + SMH_SLOT + 64 * PSTR) * 2u, vg + 64 * DMODEL, tid);
    }
    CP_COMMIT();

    CP_WAIT(2);            // Q ready
    __syncthreads();
    unsigned Qf[4][4];
#pragma unroll
    for (int kb = 0; kb < 4; ++kb) {
        unsigned addr = smb +
            ((SMH_Q + (w * 16 + (lm & 1) * 8 + lr) * PSTR + kb * 16 + (lm >> 1) * 8)) * 2u;
        ldmat4(Qf[kb][0], Qf[kb][1], Qf[kb][2], Qf[kb][3], addr);
    }

    float octx[8][4] = {};
    float l0 = 0.f, l1 = 0.f;

    for (int t = 0; t < nt; ++t) {
        CP_WAIT(1);                      // tile t arrived (t+1 may be in flight)
        __syncthreads();                 // visible to all; slot (t-1)%3 free
        if (t + 2 < nt) {
            const int is = (t + 2) % 3;
            issue_tile_h(smb + (SMH_KV + is * SMH_SLOT) * 2u,
                         kg + (long)(t + 2) * 64 * DMODEL, tid);
            issue_tile_h(smb + (SMH_KV + is * SMH_SLOT + 64 * PSTR) * 2u,
                         vg + (long)(t + 2) * 64 * DMODEL, tid);
        }
        CP_COMMIT();

        const int slot = t % 3;
        const unsigned kbase = smb + (SMH_KV + slot * SMH_SLOT) * 2u;
        const unsigned vbase = kbase + (64 * PSTR) * 2u;
        const int j0 = t * 64;
        const bool masked = (t == nt - 1) && (valid & 63);

        // ---- S = Q @ K^T (scores arrive pre-multiplied by log2e) ----
        float sacc[8][4] = {};
#pragma unroll
        for (int kb = 0; kb < 4; ++kb)
#pragma unroll
            for (int np = 0; np < 4; ++np) {
                unsigned k0, k1, k2, k3;
                unsigned addr = kbase +
                    ((np * 16 + (lm & 1) * 8 + lr) * PSTR + kb * 16 + (lm >> 1) * 8) * 2u;
                ldmat4(k0, k1, k2, k3, addr);
                mma16(sacc[2 * np],     Qf[kb], k0, k2);
                mma16(sacc[2 * np + 1], Qf[kb], k1, k3);
            }

        // ---- P = 2^S via ex2.f16x2; pack directly into A-frags ----
        unsigned pa[4][4];
        if (!masked) {
#pragma unroll
            for (int nb = 0; nb < 8; ++nb) {
                pa[nb >> 1][2 * (nb & 1)]     = ex2h2(pkh2(sacc[nb][0], sacc[nb][1]));
                pa[nb >> 1][2 * (nb & 1) + 1] = ex2h2(pkh2(sacc[nb][2], sacc[nb][3]));
            }
        } else {
#pragma unroll
            for (int nb = 0; nb < 8; ++nb) {
                const int keya = j0 + nb * 8 + 2 * t4;
                const unsigned m = (keya < valid ? 0x00003C00u : 0u) |
                                   (keya + 1 < valid ? 0x3C000000u : 0u);
                pa[nb >> 1][2 * (nb & 1)]     = hmul2u(ex2h2(pkh2(sacc[nb][0], sacc[nb][1])), m);
                pa[nb >> 1][2 * (nb & 1) + 1] = hmul2u(ex2h2(pkh2(sacc[nb][2], sacc[nb][3])), m);
            }
        }

        // ---- l += row sums of P (FMA pipe; tensor pipe is the bottleneck) ----
#pragma unroll
        for (int kb = 0; kb < 4; ++kb) {
            float2 a0 = h2f2(pa[kb][0]), a2 = h2f2(pa[kb][2]);
            float2 a1 = h2f2(pa[kb][1]), a3 = h2f2(pa[kb][3]);
            l0 += (a0.x + a0.y) + (a2.x + a2.y);
            l1 += (a1.x + a1.y) + (a3.x + a3.y);
        }

        // ---- ctx += P @ V ----
#pragma unroll
        for (int kb = 0; kb < 4; ++kb)
#pragma unroll
            for (int np = 0; np < 4; ++np) {
                unsigned v0, v1, v2, v3;
                unsigned addr = vbase +
                    ((kb * 16 + (lm & 1) * 8 + lr) * PSTR + np * 16 + (lm >> 1) * 8) * 2u;
                ldmat4t(v0, v1, v2, v3, addr);
                mma16(octx[2 * np],     pa[kb], v0, v1);
                mma16(octx[2 * np + 1], pa[kb], v2, v3);
            }
    }

    // ---- epilogue: reduce l over t4 lanes, normalize, store fp16 ----
    l0 += __shfl_xor_sync(0xffffffffu, l0, 1);
    l0 += __shfl_xor_sync(0xffffffffu, l0, 2);
    l1 += __shfl_xor_sync(0xffffffffu, l1, 1);
    l1 += __shfl_xor_sync(0xffffffffu, l1, 2);
    const float inv0 = 1.0f / l0;
    const float inv1 = 1.0f / l1;
    __half* o0 = g_ctxh + gbase + (long)(s0 + w * 16 + g) * DMODEL;
    __half* o1 = o0 + 8 * DMODEL;
#pragma unroll
    for (int nb = 0; nb < 8; ++nb) {
        int c = nb * 8 + 2 * t4;
        *(unsigned*)(o0 + c) = pkh2(octx[nb][0] * inv0, octx[nb][1] * inv0);
        *(unsigned*)(o1 + c) = pkh2(octx[nb][2] * inv1, octx[nb][3] * inv1);
    }
}

// ---------------------------------------------------------------------------
// Kernel 3: output projection out = ctx @ Wo + bo (fp16 mma, fp32 out).
// 64x64 CTAs, 3 CTAs/SM, triple-buffered cp.async (R13 — at its latency floor).
// ---------------------------------------------------------------------------
#define SMO_SLOT (64 * PSTR + 64 * PSTR)         // 9216 halfs
#define SMO_W    (64 * PSTR)
#define SMO_TOTAL (3 * SMO_SLOT * 2)             // 55296 B
#define NCHUNK (DMODEL / 64)                     // 8

__device__ __forceinline__ void issue_chunk_o(unsigned slotb, const __half* actx,
                                              const __half* awo, int tid) {
#pragma unroll
    for (int i = 0; i < 2; ++i) {
        int f = tid + i * 256, r = f >> 3, c = f & 7;
        cp16(slotb + (unsigned)(r * PSTR + c * 8) * 2u, actx + (long)r * DMODEL + c * 8);
    }
#pragma unroll
    for (int i = 0; i < 2; ++i) {
        int f = tid + i * 256, r = f >> 3, c = f & 7;
        cp16(slotb + (unsigned)(SMO_W + r * PSTR + c * 8) * 2u, awo + (long)r * DMODEL + c * 8);
    }
}

__global__ __launch_bounds__(256, 3) void outp_tc(
    const float* __restrict__ bo, float* __restrict__ out)
{
    extern __shared__ char smc[];
    const unsigned smb = (unsigned)__cvta_generic_to_shared(smc);

    const int tid = threadIdx.x, w = tid >> 5, lid = tid & 31;
    const int g = lid >> 2, t4 = lid & 3;
    const int lm = lid >> 3, lr = lid & 7;
    const int wr = w >> 1;              // row group (16 rows)
    const int wn = (w & 1) * 32;        // column half (32 cols)
    const long r0 = (long)blockIdx.y * 64;
    const int n0 = blockIdx.x * 64;

    const __half* actx = g_ctxh + r0 * DMODEL;
    const __half* awo  = g_woh + n0;

    issue_chunk_o(smb, actx, awo, tid);
    CP_COMMIT();
    issue_chunk_o(smb + SMO_SLOT * 2u, actx + 64, awo + 64 * DMODEL, tid);
    CP_COMMIT();

    float acc[4][4] = {};
    for (int t = 0; t < NCHUNK; ++t) {
        CP_WAIT(1);
        __syncthreads();
        if (t + 2 < NCHUNK) {
            const int is = (t + 2) % 3;
            issue_chunk_o(smb + (unsigned)(is * SMO_SLOT) * 2u,
                          actx + (t + 2) * 64, awo + (long)(t + 2) * 64 * DMODEL, tid);
        }
        CP_COMMIT();

        const unsigned abase = smb + (unsigned)((t % 3) * SMO_SLOT) * 2u;
        const unsigned wbase = abase + (unsigned)SMO_W * 2u;

#pragma unroll
        for (int kb = 0; kb < 4; ++kb) {
            unsigned af[4];
            unsigned aaddr = abase +
                ((16 * wr + (lm & 1) * 8 + lr) * PSTR + kb * 16 + (lm >> 1) * 8) * 2u;
            ldmat4(af[0], af[1], af[2], af[3], aaddr);
#pragma unroll
            for (int np = 0; np < 2; ++np) {
                unsigned v0, v1, v2, v3;
                unsigned addr = wbase +
                    ((kb * 16 + (lm & 1) * 8 + lr) * PSTR + wn + np * 16 + (lm >> 1) * 8) * 2u;
                ldmat4t(v0, v1, v2, v3, addr);
                mma16(acc[2 * np],     af, v0, v1);
                mma16(acc[2 * np + 1], af, v2, v3);
            }
        }
    }

    const long row0 = (r0 + 16 * wr + g) * DMODEL + n0 + wn;
    const long row1 = row0 + 8 * DMODEL;
#pragma unroll
    for (int nb = 0; nb < 4; ++nb) {
        int c = nb * 8 + 2 * t4;
        float b0v = bo[n0 + wn + c], b1v = bo[n0 + wn + c + 1];
        *(float2*)(out + row0 + c) = make_float2(acc[nb][0] + b0v, acc[nb][1] + b1v);
        *(float2*)(out + row1 + c) = make_float2(acc[nb][2] + b0v, acc[nb][3] + b1v);
    }
}

// ---------------------------------------------------------------------------
// launch
// inputs: 0:q 1:k 2:v 3:Wq 4:bq 5:Wk 6:bk 7:Wv 8:bv 9:Wo 10:bo 11:valid_lens 12:max_len
// ---------------------------------------------------------------------------
extern "C" void kernel_launch(void* const* d_in, const int* in_sizes, int n_in,
                              void* d_out, int out_size)
{
    const float* q  = (const float*)d_in[0];
    const float* k  = (const float*)d_in[1];
    const float* v  = (const float*)d_in[2];
    const float* Wq = (const float*)d_in[3];
    const float* bq = (const float*)d_in[4];
    const float* Wk = (const float*)d_in[5];
    const float* bk = (const float*)d_in[6];
    const float* Wv = (const float*)d_in[7];
    const float* bv = (const float*)d_in[8];
    const float* Wo = (const float*)d_in[9];
    const float* bo = (const float*)d_in[10];
    const int* valid_lens = (const int*)d_in[11];
    float* out = (float*)d_out;

    const int B = in_sizes[11];
    const int S = in_sizes[0] / (B * DMODEL);
    const int BS = B * S;

    const int smProj = (2 * 128 * PSTR + 64 * PSTR) * 2;   // 46080 B

    // 0) Wo -> fp16 (one-time per launch)
    cvt_wo<<<DMODEL * DMODEL / 1024, 256>>>(Wo);

    // 1) projections (2 row-blocks per CTA, register prefetch)
    cudaFuncSetAttribute(proj_tc, cudaFuncAttributeMaxDynamicSharedMemorySize, smProj);
    proj_tc<<<dim3(BS * 8 / (128 * PBLK), 3), 256, smProj>>>(q, k, v, Wq, Wk, Wv, bq, bk, bv);

    // 2) fp16 flash attention (2 CTAs/SM, triple-buffered cp.async)
    cudaFuncSetAttribute(attn_mma, cudaFuncAttributeMaxDynamicSharedMemorySize, SMH_TOTAL);
    attn_mma<<<dim3(S / 128, NHEAD, B), 256, SMH_TOTAL>>>(valid_lens, S);

    // 3) output projection (64x64 tiles, 3 CTAs/SM, triple-buffered)
    cudaFuncSetAttribute(outp_tc, cudaFuncAttributeMaxDynamicSharedMemorySize, SMO_TOTAL);
    outp_tc<<<dim3(DMODEL / 64, BS / 64), 256, SMO_TOTAL>>>(bo, out);
}

// round 15
// speedup vs baseline: 1.0634x; 1.0634x over previous
#include <cuda_runtime.h>
#include <cuda_fp16.h>
#include <stdint.h>

#define NHEAD 8
#define DMODEL 512
#define MAXELEMS (4*2048*512)

// Scratch (allocation-free rule: __device__ globals) — fp16 activations
__device__ __half g_qph[MAXELEMS];   // pre-scaled by 0.125*log2(e)
__device__ __half g_kph[MAXELEMS];
__device__ __half g_vph[MAXELEMS];
__device__ __half g_ctxh[MAXELEMS];
__device__ __half g_woh[DMODEL * DMODEL];

// ---------------------------------------------------------------------------
// fp16 mma + ldmatrix helpers (legacy path: valid on plain sm_103 target)
// ---------------------------------------------------------------------------
__device__ __forceinline__ void mma16(float c[4], const unsigned a[4],
                                      unsigned b0, unsigned b1) {
    asm volatile("mma.sync.aligned.m16n8k16.row.col.f32.f16.f16.f32 "
                 "{%0,%1,%2,%3}, {%4,%5,%6,%7}, {%8,%9}, {%0,%1,%2,%3};"
                 : "+f"(c[0]), "+f"(c[1]), "+f"(c[2]), "+f"(c[3])
                 : "r"(a[0]), "r"(a[1]), "r"(a[2]), "r"(a[3]), "r"(b0), "r"(b1));
}
// fp16 accumulator variant: C/D are 2 regs (4 halfs), laid out as half2 pairs
// {row g: cols 2t4,2t4+1} and {row g+8: cols 2t4,2t4+1} — the P A-frag layout.
__device__ __forceinline__ void mma16h(unsigned c[2], const unsigned a[4],
                                       unsigned b0, unsigned b1) {
    asm volatile("mma.sync.aligned.m16n8k16.row.col.f16.f16.f16.f16 "
                 "{%0,%1}, {%2,%3,%4,%5}, {%6,%7}, {%0,%1};"
                 : "+r"(c[0]), "+r"(c[1])
                 : "r"(a[0]), "r"(a[1]), "r"(a[2]), "r"(a[3]), "r"(b0), "r"(b1));
}
__device__ __forceinline__ void ldmat4(unsigned& r0, unsigned& r1,
                                       unsigned& r2, unsigned& r3, unsigned addr) {
    asm volatile("ldmatrix.sync.aligned.m8n8.x4.shared.b16 {%0,%1,%2,%3}, [%4];"
                 : "=r"(r0), "=r"(r1), "=r"(r2), "=r"(r3) : "r"(addr));
}
__device__ __forceinline__ void ldmat4t(unsigned& r0, unsigned& r1,
                                        unsigned& r2, unsigned& r3, unsigned addr) {
    asm volatile("ldmatrix.sync.aligned.m8n8.x4.trans.shared.b16 {%0,%1,%2,%3}, [%4];"
                 : "=r"(r0), "=r"(r1), "=r"(r2), "=r"(r3) : "r"(addr));
}
__device__ __forceinline__ unsigned pkh2(float a, float b) {
    __half2 h = __floats2half2_rn(a, b);
    return *reinterpret_cast<unsigned*>(&h);
}
__device__ __forceinline__ unsigned ex2h2(unsigned x) {
    unsigned r;
    asm("ex2.approx.f16x2 %0, %1;" : "=r"(r) : "r"(x));
    return r;
}
__device__ __forceinline__ unsigned hmul2u(unsigned a, unsigned b) {
    __half2 r = __hmul2(*reinterpret_cast<__half2*>(&a), *reinterpret_cast<__half2*>(&b));
    return *reinterpret_cast<unsigned*>(&r);
}
#define ONES2 0x3C003C00u   // half2(1.0, 1.0)

// cp.async helpers
__device__ __forceinline__ void cp16(unsigned dst, const void* src) {
    asm volatile("cp.async.cg.shared.global [%0], [%1], 16;" :: "r"(dst), "l"(src));
}
#define CP_COMMIT() asm volatile("cp.async.commit_group;" ::: "memory")
#define CP_WAIT(n)  asm volatile("cp.async.wait_group %0;" :: "n"(n) : "memory")

// pane row stride: 72 halfs (36 half2; 36 mod 32 = 4 -> conflict-free frags;
// 144 B rows = 9 x 16B -> ldmatrix-aligned, conflict-free phases)
#define PSTR 72
#define PSTR2 36

// ---------------------------------------------------------------------------
// Kernel 1: projections (x viewed as [BS*8, 64] rows; W shared across heads).
// blockIdx.y == 3 branch converts Wo fp32 -> fp16 (fused, saves a launch).
// q output pre-scaled by 0.125*log2(e) so attention scores are base-2 ready.
// ---------------------------------------------------------------------------
__global__ __launch_bounds__(256) void proj_tc(
    const float* __restrict__ q, const float* __restrict__ k, const float* __restrict__ v,
    const float* __restrict__ Wq, const float* __restrict__ Wk, const float* __restrict__ Wv,
    const float* __restrict__ bq, const float* __restrict__ bk, const float* __restrict__ bv,
    const float* __restrict__ Wo)
{
    extern __shared__ char smc[];
    const int tid = threadIdx.x;
    const int which = blockIdx.y;

    if (which == 3) {   // Wo conversion: 512 CTAs x 256 thr x 2 floats
        int i = (blockIdx.x * 256 + tid) * 2;
        float2 a = *(const float2*)(Wo + i);
        *(unsigned*)&g_woh[i] = pkh2(a.x, a.y);
        return;
    }

    __half* As = (__half*)smc;                // [128][72]
    __half* Ws = (__half*)smc + 128 * PSTR;   // [64][72]

    const int w = tid >> 5, lid = tid & 31;
    const int g = lid >> 2, t4 = lid & 3;
    const float* x  = which == 0 ? q  : which == 1 ? k  : v;
    const float* W  = which == 0 ? Wq : which == 1 ? Wk : Wv;
    const float* bb = which == 0 ? bq : which == 1 ? bk : bv;
    __half* dst = which == 0 ? g_qph : which == 1 ? g_kph : g_vph;
    const float scale = which == 0 ? 0.125f * 1.4426950408889634f : 1.0f;
    const long r0 = (long)blockIdx.x * 128;

#pragma unroll
    for (int i = 0; i < 8; ++i) {
        int f = tid + i * 256, r = f >> 4, c = f & 15;
        float4 a = *(const float4*)(x + (r0 + r) * 64 + c * 4);
        *(uint2*)&As[r * PSTR + c * 4] = make_uint2(pkh2(a.x, a.y), pkh2(a.z, a.w));
    }
#pragma unroll
    for (int i = 0; i < 4; ++i) {
        int f = tid + i * 256, r = f >> 4, c = f & 15;
        float4 a = *(const float4*)(W + r * 64 + c * 4);
        *(uint2*)&Ws[r * PSTR + c * 4] = make_uint2(pkh2(a.x, a.y), pkh2(a.z, a.w));
    }
    __syncthreads();

    const int lm = lid >> 3, lr = lid & 7;
    const unsigned abase = (unsigned)__cvta_generic_to_shared(As);
    const unsigned wbase = (unsigned)__cvta_generic_to_shared(Ws);

    unsigned af[4][4];
#pragma unroll
    for (int kb = 0; kb < 4; ++kb) {
        unsigned addr = abase +
            ((16 * w + (lm & 1) * 8 + lr) * PSTR + kb * 16 + (lm >> 1) * 8) * 2u;
        ldmat4(af[kb][0], af[kb][1], af[kb][2], af[kb][3], addr);
    }

    float acc[8][4] = {};
#pragma unroll
    for (int kb = 0; kb < 4; ++kb)
#pragma unroll
        for (int np = 0; np < 4; ++np) {
            unsigned v0, v1, v2, v3;
            unsigned addr = wbase +
                ((kb * 16 + (lm & 1) * 8 + lr) * PSTR + np * 16 + (lm >> 1) * 8) * 2u;
            ldmat4t(v0, v1, v2, v3, addr);
            mma16(acc[2 * np],     af[kb], v0, v1);
            mma16(acc[2 * np + 1], af[kb], v2, v3);
        }

    const long row0 = (r0 + 16 * w + g) * 64;
    const long row1 = row0 + 8 * 64;
#pragma unroll
    for (int nb = 0; nb < 8; ++nb) {
        int c = nb * 8 + 2 * t4;
        float b0v = bb[c], b1v = bb[c + 1];
        *(unsigned*)(dst + row0 + c) = pkh2((acc[nb][0] + b0v) * scale, (acc[nb][1] + b1v) * scale);
        *(unsigned*)(dst + row1 + c) = pkh2((acc[nb][2] + b0v) * scale, (acc[nb][3] + b1v) * scale);
    }
}

// ---------------------------------------------------------------------------
// Kernel 2: fp16 flash attention, triple-buffered K/V, ONE barrier per tile.
// QK uses fp16-ACCUMULATOR mma: C-frags come out pre-packed as the P A-frags
// (no pkh2), and tests whether fp16-acc HMMA is double-rate on sm_103.
// PV stays fp32-acc. l via P@ones mma (R13 best).
// ---------------------------------------------------------------------------
#define SMH_Q 0
#define SMH_SLOT (2 * 64 * PSTR)               // 9216 halfs per slot (K+V)
#define SMH_KV (128 * PSTR)                    // slots start after Q
#define SMH_TOTAL ((SMH_KV + 3 * SMH_SLOT) * 2)  // 73728 B

__device__ __forceinline__ void issue_tile_h(unsigned dstb, const __half* gsrc, int tid) {
#pragma unroll
    for (int i = 0; i < 2; ++i) {
        int f = tid + i * 256, r = f >> 3, c = f & 7;
        cp16(dstb + (unsigned)(r * PSTR + c * 8) * 2u, gsrc + (long)r * DMODEL + c * 8);
    }
}

__global__ __launch_bounds__(256, 2) void attn_mma(const int* __restrict__ valid_lens, int S)
{
    extern __shared__ char smc[];
    const unsigned smb = (unsigned)__cvta_generic_to_shared(smc);

    const int tid = threadIdx.x, w = tid >> 5, lid = tid & 31;
    const int g = lid >> 2, t4 = lid & 3;
    const int lm = lid >> 3, lr = lid & 7;

    const int h = blockIdx.y, b = blockIdx.z;
    const int s0 = blockIdx.x * 128;
    const int valid = valid_lens[b];
    const long gbase = (long)b * S * DMODEL + h * 64;
    const __half* kg = g_kph + gbase;
    const __half* vg = g_vph + gbase;

    const int nt = (valid + 63) >> 6;

    // G0: Q tile [128 x 64]
#pragma unroll
    for (int i = 0; i < 4; ++i) {
        int f = tid + i * 256, r = f >> 3, c = f & 7;
        cp16(smb + (unsigned)(SMH_Q + r * PSTR + c * 8) * 2u,
             g_qph + gbase + (long)(s0 + r) * DMODEL + c * 8);
    }
    CP_COMMIT();
    // G1: tile0 -> slot0; G2: tile1 -> slot1 (maybe empty)
    issue_tile_h(smb + SMH_KV * 2u, kg, tid);
    issue_tile_h(smb + (SMH_KV + 64 * PSTR) * 2u, vg, tid);
    CP_COMMIT();
    if (nt > 1) {
        issue_tile_h(smb + (SMH_KV + SMH_SLOT) * 2u, kg + 64 * DMODEL, tid);
        issue_tile_h(smb + (SMH_KV + SMH_SLOT + 64 * PSTR) * 2u, vg + 64 * DMODEL, tid);
    }
    CP_COMMIT();

    CP_WAIT(2);            // Q ready
    __syncthreads();
    unsigned Qf[4][4];
#pragma unroll
    for (int kb = 0; kb < 4; ++kb) {
        unsigned addr = smb +
            ((SMH_Q + (w * 16 + (lm & 1) * 8 + lr) * PSTR + kb * 16 + (lm >> 1) * 8)) * 2u;
        ldmat4(Qf[kb][0], Qf[kb][1], Qf[kb][2], Qf[kb][3], addr);
    }

    float octx[8][4] = {};
    float lacc[4] = {};    // softmax denominators via P @ ones

    for (int t = 0; t < nt; ++t) {
        CP_WAIT(1);                      // tile t arrived (t+1 may be in flight)
        __syncthreads();                 // visible to all; slot (t-1)%3 free
        if (t + 2 < nt) {
            const int is = (t + 2) % 3;
            issue_tile_h(smb + (SMH_KV + is * SMH_SLOT) * 2u,
                         kg + (long)(t + 2) * 64 * DMODEL, tid);
            issue_tile_h(smb + (SMH_KV + is * SMH_SLOT + 64 * PSTR) * 2u,
                         vg + (long)(t + 2) * 64 * DMODEL, tid);
        }
        CP_COMMIT();

        const int slot = t % 3;
        const unsigned kbase = smb + (SMH_KV + slot * SMH_SLOT) * 2u;
        const unsigned vbase = kbase + (64 * PSTR) * 2u;
        const int j0 = t * 64;
        const bool masked = (t == nt - 1) && (valid & 63);

        // ---- S = Q @ K^T (fp16 accumulator; scores pre-multiplied by log2e) ----
        unsigned sh[8][2] = {};          // fp16x2 C-frags, zero-init
#pragma unroll
        for (int kb = 0; kb < 4; ++kb)
#pragma unroll
            for (int np = 0; np < 4; ++np) {
                unsigned k0, k1, k2, k3;
                unsigned addr = kbase +
                    ((np * 16 + (lm & 1) * 8 + lr) * PSTR + kb * 16 + (lm >> 1) * 8) * 2u;
                ldmat4(k0, k1, k2, k3, addr);
                mma16h(sh[2 * np],     Qf[kb], k0, k2);
                mma16h(sh[2 * np + 1], Qf[kb], k1, k3);
            }

        // ---- P = 2^S via ex2.f16x2 directly on packed C-frags ----
        unsigned pa[4][4];
        if (!masked) {
#pragma unroll
            for (int nb = 0; nb < 8; ++nb) {
                pa[nb >> 1][2 * (nb & 1)]     = ex2h2(sh[nb][0]);
                pa[nb >> 1][2 * (nb & 1) + 1] = ex2h2(sh[nb][1]);
            }
        } else {
#pragma unroll
            for (int nb = 0; nb < 8; ++nb) {
                const int keya = j0 + nb * 8 + 2 * t4;
                const unsigned m = (keya < valid ? 0x00003C00u : 0u) |
                                   (keya + 1 < valid ? 0x3C000000u : 0u);
                pa[nb >> 1][2 * (nb & 1)]     = hmul2u(ex2h2(sh[nb][0]), m);
                pa[nb >> 1][2 * (nb & 1) + 1] = hmul2u(ex2h2(sh[nb][1]), m);
            }
        }

        // ---- l += P @ ones (row sums, fp32, accumulated across tiles) ----
#pragma unroll
        for (int kb = 0; kb < 4; ++kb)
            mma16(lacc, pa[kb], ONES2, ONES2);

        // ---- ctx += P @ V (fp32 accumulator) ----
#pragma unroll
        for (int kb = 0; kb < 4; ++kb)
#pragma unroll
            for (int np = 0; np < 4; ++np) {
                unsigned v0, v1, v2, v3;
                unsigned addr = vbase +
                    ((kb * 16 + (lm & 1) * 8 + lr) * PSTR + np * 16 + (lm >> 1) * 8) * 2u;
                ldmat4t(v0, v1, v2, v3, addr);
                mma16(octx[2 * np],     pa[kb], v0, v1);
                mma16(octx[2 * np + 1], pa[kb], v2, v3);
            }
    }

    // ---- epilogue: normalize (denominators already reduced by mma) ----
    const float inv0 = 1.0f / lacc[0];
    const float inv1 = 1.0f / lacc[2];
    __half* o0 = g_ctxh + gbase + (long)(s0 + w * 16 + g) * DMODEL;
    __half* o1 = o0 + 8 * DMODEL;
#pragma unroll
    for (int nb = 0; nb < 8; ++nb) {
        int c = nb * 8 + 2 * t4;
        *(unsigned*)(o0 + c) = pkh2(octx[nb][0] * inv0, octx[nb][1] * inv0);
        *(unsigned*)(o1 + c) = pkh2(octx[nb][2] * inv1, octx[nb][3] * inv1);
    }
}

// ---------------------------------------------------------------------------
// Kernel 3: output projection out = ctx @ Wo + bo (fp16 mma, fp32 out).
// 64x64 CTAs, 3 CTAs/SM, triple-buffered cp.async (R13 configuration).
// ---------------------------------------------------------------------------
#define SMO_SLOT (64 * PSTR + 64 * PSTR)         // 9216 halfs
#define SMO_W    (64 * PSTR)
#define SMO_TOTAL (3 * SMO_SLOT * 2)             // 55296 B
#define NCHUNK (DMODEL / 64)                     // 8

__device__ __forceinline__ void issue_chunk_o(unsigned slotb, const __half* actx,
                                              const __half* awo, int tid) {
#pragma unroll
    for (int i = 0; i < 2; ++i) {
        int f = tid + i * 256, r = f >> 3, c = f & 7;
        cp16(slotb + (unsigned)(r * PSTR + c * 8) * 2u, actx + (long)r * DMODEL + c * 8);
    }
#pragma unroll
    for (int i = 0; i < 2; ++i) {
        int f = tid + i * 256, r = f >> 3, c = f & 7;
        cp16(slotb + (unsigned)(SMO_W + r * PSTR + c * 8) * 2u, awo + (long)r * DMODEL + c * 8);
    }
}

__global__ __launch_bounds__(256, 3) void outp_tc(
    const float* __restrict__ bo, float* __restrict__ out)
{
    extern __shared__ char smc[];
    const unsigned smb = (unsigned)__cvta_generic_to_shared(smc);

    const int tid = threadIdx.x, w = tid >> 5, lid = tid & 31;
    const int g = lid >> 2, t4 = lid & 3;
    const int lm = lid >> 3, lr = lid & 7;
    const int wr = w >> 1;              // row group (16 rows)
    const int wn = (w & 1) * 32;        // column half (32 cols)
    const long r0 = (long)blockIdx.y * 64;
    const int n0 = blockIdx.x * 64;

    const __half* actx = g_ctxh + r0 * DMODEL;
    const __half* awo  = g_woh + n0;

    issue_chunk_o(smb, actx, awo, tid);
    CP_COMMIT();
    issue_chunk_o(smb + SMO_SLOT * 2u, actx + 64, awo + 64 * DMODEL, tid);
    CP_COMMIT();

    float acc[4][4] = {};
    for (int t = 0; t < NCHUNK; ++t) {
        CP_WAIT(1);
        __syncthreads();
        if (t + 2 < NCHUNK) {
            const int is = (t + 2) % 3;
            issue_chunk_o(smb + (unsigned)(is * SMO_SLOT) * 2u,
                          actx + (t + 2) * 64, awo + (long)(t + 2) * 64 * DMODEL, tid);
        }
        CP_COMMIT();

        const unsigned abase = smb + (unsigned)((t % 3) * SMO_SLOT) * 2u;
        const unsigned wbase = abase + (unsigned)SMO_W * 2u;

#pragma unroll
        for (int kb = 0; kb < 4; ++kb) {
            unsigned af[4];
            unsigned aaddr = abase +
                ((16 * wr + (lm & 1) * 8 + lr) * PSTR + kb * 16 + (lm >> 1) * 8) * 2u;
            ldmat4(af[0], af[1], af[2], af[3], aaddr);
#pragma unroll
            for (int np = 0; np < 2; ++np) {
                unsigned v0, v1, v2, v3;
                unsigned addr = wbase +
                    ((kb * 16 + (lm & 1) * 8 + lr) * PSTR + wn + np * 16 + (lm >> 1) * 8) * 2u;
                ldmat4t(v0, v1, v2, v3, addr);
                mma16(acc[2 * np],     af, v0, v1);
                mma16(acc[2 * np + 1], af, v2, v3);
            }
        }
    }

    const long row0 = (r0 + 16 * wr + g) * DMODEL + n0 + wn;
    const long row1 = row0 + 8 * DMODEL;
#pragma unroll
    for (int nb = 0; nb < 4; ++nb) {
        int c = nb * 8 + 2 * t4;
        float b0v = bo[n0 + wn + c], b1v = bo[n0 + wn + c + 1];
        *(float2*)(out + row0 + c) = make_float2(acc[nb][0] + b0v, acc[nb][1] + b1v);
        *(float2*)(out + row1 + c) = make_float2(acc[nb][2] + b0v, acc[nb][3] + b1v);
    }
}

// ---------------------------------------------------------------------------
// launch
// inputs: 0:q 1:k 2:v 3:Wq 4:bq 5:Wk 6:bk 7:Wv 8:bv 9:Wo 10:bo 11:valid_lens 12:max_len
// ---------------------------------------------------------------------------
extern "C" void kernel_launch(void* const* d_in, const int* in_sizes, int n_in,
                              void* d_out, int out_size)
{
    const float* q  = (const float*)d_in[0];
    const float* k  = (const float*)d_in[1];
    const float* v  = (const float*)d_in[2];
    const float* Wq = (const float*)d_in[3];
    const float* bq = (const float*)d_in[4];
    const float* Wk = (const float*)d_in[5];
    const float* bk = (const float*)d_in[6];
    const float* Wv = (const float*)d_in[7];
    const float* bv = (const float*)d_in[8];
    const float* Wo = (const float*)d_in[9];
    const float* bo = (const float*)d_in[10];
    const int* valid_lens = (const int*)d_in[11];
    float* out = (float*)d_out;

    const int B = in_sizes[11];
    const int S = in_sizes[0] / (B * DMODEL);
    const int BS = B * S;

    const int smGemm = (128 * PSTR + 64 * PSTR) * 2;   // 27648 B

    // 1) projections + fused Wo conversion (blockIdx.y == 3)
    cudaFuncSetAttribute(proj_tc, cudaFuncAttributeMaxDynamicSharedMemorySize, smGemm);
    proj_tc<<<dim3(BS * 8 / 128, 4), 256, smGemm>>>(q, k, v, Wq, Wk, Wv, bq, bk, bv, Wo);

    // 2) fp16 flash attention (fp16-acc QK, 2 CTAs/SM, triple-buffered)
    cudaFuncSetAttribute(attn_mma, cudaFuncAttributeMaxDynamicSharedMemorySize, SMH_TOTAL);
    attn_mma<<<dim3(S / 128, NHEAD, B), 256, SMH_TOTAL>>>(valid_lens, S);

    // 3) output projection (64x64 tiles, 3 CTAs/SM, triple-buffered)
    cudaFuncSetAttribute(outp_tc, cudaFuncAttributeMaxDynamicSharedMemorySize, SMO_TOTAL);
    outp_tc<<<dim3(DMODEL / 64, BS / 64), 256, SMO_TOTAL>>>(bo, out);
}